// round 12
// baseline (speedup 1.0000x reference)
#include <cuda_runtime.h>
#include <cstdint>

// Embedding gather + sinusoidal positional encoding.
// out[row, c] = W[ids[row], c] + (row even ? sin : cos)(row * freq(c)),
//   freq(c) = 10000^(-2c/D)
//
// D = 1024, TOKENS = 8192. Grid = 2048 CTAs x 4 rows, 256 threads.
// This round: register diet (<=32 regs via __launch_bounds__(256,8)) to reach
// 8 CTAs/SM -> n_conc=1184 -> 2 waves instead of 3. PE is fused directly into
// the gathered values column-by-column (no pe[] staging arrays); per-row PE
// values are independent (angle addition + double/triple-angle identities).

static constexpr int D       = 1024;
static constexpr int VEC     = 4;
static constexpr int THREADS = D / VEC;   // 256
static constexpr int R       = 4;         // rows per block

// sincos for 0 <= x <= ~8200: 3-term Cody-Waite reduction mod 2*pi, then MUFU.
__device__ __forceinline__ void fast_sincos(float x, float& s, float& c)
{
    const float INV2PI = 0.15915494309189535f;
    const float C1 = 6.28125f;
    const float C2 = 1.93530717957e-3f;
    const float C3 = 6.1232339957e-10f;
    float q = rintf(x * INV2PI);
    float a = fmaf(-q, C1, x);
    a = fmaf(-q, C2, a);
    a = fmaf(-q, C3, a);
    s = __sinf(a);
    c = __cosf(a);
}

__global__ __launch_bounds__(THREADS, 8)
void emb_pe_kernel(const int* __restrict__ ids,
                   const float* __restrict__ W,
                   float* __restrict__ out)
{
    const int row0 = blockIdx.x * R;          // multiple of 4 -> even
    const int t    = threadIdx.x;             // 0..255
    const int c0   = t * VEC;                 // starting column

    // One 16B load covers this CTA's 4 ids.
    const int4 ii = *reinterpret_cast<const int4*>(ids + row0);

    const float* Wc = W + c0;

    // Front-batch all 4 gathers (independent LDG.128, MLP=4).
    float4 v0 = *reinterpret_cast<const float4*>(Wc + (size_t)ii.x * D);
    float4 v1 = *reinterpret_cast<const float4*>(Wc + (size_t)ii.y * D);
    float4 v2 = *reinterpret_cast<const float4*>(Wc + (size_t)ii.z * D);
    float4 v3 = *reinterpret_cast<const float4*>(Wc + (size_t)ii.w * D);

    // PE fused in place, column by column (temps reuse across columns).
    // freq(c) = 2^(kexp * c),  kexp = -2*log2(10000)/D
    const float kexp = -13.287712379549449f * 2.0f / (float)D;
    const float pos0 = (float)row0;

    float* p0 = &v0.x;
    float* p1 = &v1.x;
    float* p2 = &v2.x;
    float* p3 = &v3.x;

#pragma unroll
    for (int i = 0; i < VEC; i++) {
        float freq = exp2f(kexp * (float)(c0 + i));
        float s0, cc0, sd, cd;
        fast_sincos(pos0 * freq, s0, cc0);    // seed at row0
        fast_sincos(freq,        sd, cd);     // +1 row delta
        // double / triple angle (pure FMA):
        float s2d = 2.0f * sd * cd;
        float c2d = fmaf(-2.0f * sd, sd, 1.0f);
        float s3d = fmaf(s2d, cd,  c2d * sd);
        float c3d = fmaf(c2d, cd, -s2d * sd);
        // fuse PE into gathered values:
        p0[i] += s0;                           // sin(row0 * f)
        p1[i] += fmaf(cc0, cd, -s0 * sd);      // cos((row0+1) f)
        p2[i] += fmaf(s0, c2d,  cc0 * s2d);    // sin((row0+2) f)
        p3[i] += fmaf(cc0, c3d, -s0 * s3d);    // cos((row0+3) f)
    }

    float* outp = out + (size_t)row0 * D + c0;
    *reinterpret_cast<float4*>(outp)         = v0;
    *reinterpret_cast<float4*>(outp + D)     = v1;
    *reinterpret_cast<float4*>(outp + 2 * D) = v2;
    *reinterpret_cast<float4*>(outp + 3 * D) = v3;
}

extern "C" void kernel_launch(void* const* d_in, const int* in_sizes, int n_in,
                              void* d_out, int out_size)
{
    const int*   ids = (const int*)d_in[0];
    const float* W   = (const float*)d_in[1];
    float*       out = (float*)d_out;

    const int rows = in_sizes[0];             // 8192 tokens
    emb_pe_kernel<<<rows / R, THREADS>>>(ids, W, out);
}